// round 2
// baseline (speedup 1.0000x reference)
#include <cuda_runtime.h>
#include <cstdint>

#define BB 32
#define LL 2048
#define DD 64
#define QT 64          // queries per CTA in qk/pv kernels
#define KTILE 128      // keys per smem tile
#define NKT (LL / KTILE)

#define QTP 68         // padded stride for transposed q tile (floats)
#define KTP 132        // padded stride for transposed k tile (floats)
#define SSP 132        // padded stride for score tile rows (floats)
#define VSP 68         // padded stride for v tile rows (floats)

// Scratch (device globals — no allocation allowed)
__device__ float g_qn[(size_t)BB * LL * DD];
__device__ float g_kn[(size_t)BB * LL * DD];
__device__ float g_rinv[(size_t)BB * LL];

// ---------- f32x2 packed helpers ----------
union F4U2 { float4 f; ulonglong2 u; };

__device__ __forceinline__ unsigned long long pack2(float lo, float hi) {
    unsigned long long r;
    asm("mov.b64 %0, {%1, %2};" : "=l"(r) : "f"(lo), "f"(hi));
    return r;
}
__device__ __forceinline__ void fma2(unsigned long long& d,
                                     unsigned long long a,
                                     unsigned long long b) {
    asm("fma.rn.f32x2 %0, %1, %2, %0;" : "+l"(d) : "l"(a), "l"(b));
}
__device__ __forceinline__ float2 unpack2(unsigned long long v) {
    float2 f;
    asm("mov.b64 {%0, %1}, %2;" : "=f"(f.x), "=f"(f.y) : "l"(v));
    return f;
}

// ---------- Kernel 1: L2-normalize q and k rows ----------
// grid: 2*B*L/16 blocks of 256 threads; 16 threads per row (float4 each)
__global__ __launch_bounds__(256) void norm_kernel(const float* __restrict__ q,
                                                   const float* __restrict__ k) {
    int t = threadIdx.x;
    int rowInBlk = t >> 4;
    int lane = t & 15;
    long long row = (long long)blockIdx.x * 16 + rowInBlk;

    const float* src;
    float* dst;
    long long r2 = row;
    if (r2 < (long long)BB * LL) {
        src = q; dst = g_qn;
    } else {
        src = k; dst = g_kn; r2 -= (long long)BB * LL;
    }

    const float4 v = *(const float4*)(src + r2 * DD + lane * 4);
    float ss = v.x * v.x + v.y * v.y + v.z * v.z + v.w * v.w;
#pragma unroll
    for (int o = 8; o; o >>= 1) ss += __shfl_xor_sync(0xffffffffu, ss, o, 16);
    float nrm = sqrtf(ss);
    float inv = 1.0f / fmaxf(nrm, 1e-12f);
    float4 o4 = make_float4(v.x * inv, v.y * inv, v.z * inv, v.w * inv);
    *(float4*)(dst + r2 * DD + lane * 4) = o4;
}

// ---------- Kernel 2: QK scores (raw, masked, +1) + row sums ----------
// grid: (L/QT, B), 256 threads. Thread tile: 4q x 8k.
// dyn smem: qT[64][QTP] + kT[64][KTP]
__global__ __launch_bounds__(256) void qk_kernel(const int* __restrict__ mask,
                                                 float* __restrict__ attn) {
    extern __shared__ float sm[];
    float* qT = sm;                 // transposed q tile [d][qy]
    float* kT = sm + DD * QTP;      // transposed k tile [d][kx]

    int b = blockIdx.y;
    int q0 = blockIdx.x * QT;
    int t = threadIdx.x;
    int ty = t >> 4;   // 0..15 (q group of 4)
    int tx = t & 15;   // 0..15 (k group of 8)

    // Load + transpose q tile (64 rows x 64)
    const float* qn = g_qn + ((size_t)b * LL + q0) * DD;
#pragma unroll
    for (int i = 0; i < 4; i++) {
        int idx = i * 256 + t;
        int r = idx >> 4, c4 = idx & 15;
        float4 w = *(const float4*)(qn + r * DD + c4 * 4);
        qT[(c4 * 4 + 0) * QTP + r] = w.x;
        qT[(c4 * 4 + 1) * QTP + r] = w.y;
        qT[(c4 * 4 + 2) * QTP + r] = w.z;
        qT[(c4 * 4 + 3) * QTP + r] = w.w;
    }

    const float* kn = g_kn + (size_t)b * LL * DD;
    float rs[4] = {0.f, 0.f, 0.f, 0.f};

    for (int kt = 0; kt < NKT; kt++) {
        __syncthreads();
        // Load + transpose k tile (128 rows x 64)
#pragma unroll
        for (int i = 0; i < 8; i++) {
            int idx = i * 256 + t;
            int r = idx >> 4, c4 = idx & 15;
            float4 w = *(const float4*)(kn + ((size_t)kt * KTILE + r) * DD + c4 * 4);
            kT[(c4 * 4 + 0) * KTP + r] = w.x;
            kT[(c4 * 4 + 1) * KTP + r] = w.y;
            kT[(c4 * 4 + 2) * KTP + r] = w.z;
            kT[(c4 * 4 + 3) * KTP + r] = w.w;
        }
        __syncthreads();

        unsigned long long acc[4][4];
#pragma unroll
        for (int i = 0; i < 4; i++)
#pragma unroll
            for (int j = 0; j < 4; j++) acc[i][j] = 0ull;

#pragma unroll 8
        for (int d = 0; d < DD; d++) {
            float4 qf = *(const float4*)&qT[d * QTP + ty * 4];
            F4U2 ka, kb;
            ka.f = *(const float4*)&kT[d * KTP + tx * 8];
            kb.f = *(const float4*)&kT[d * KTP + tx * 8 + 4];
            unsigned long long kk0 = ka.u.x, kk1 = ka.u.y, kk2 = kb.u.x, kk3 = kb.u.y;
            float qv[4] = {qf.x, qf.y, qf.z, qf.w};
#pragma unroll
            for (int i = 0; i < 4; i++) {
                unsigned long long qq = pack2(qv[i], qv[i]);
                fma2(acc[i][0], qq, kk0);
                fma2(acc[i][1], qq, kk1);
                fma2(acc[i][2], qq, kk2);
                fma2(acc[i][3], qq, kk3);
            }
        }

        // Epilogue: mask (int32 0/1), +1, write raw scores, accumulate row sums
        size_t kbase = (size_t)kt * KTILE + tx * 8;
#pragma unroll
        for (int i = 0; i < 4; i++) {
            int qrow = q0 + ty * 4 + i;
            const int* mrow = mask + ((size_t)b * LL + qrow) * LL + kbase;
            int4 m0 = *(const int4*)mrow;
            int4 m1 = *(const int4*)(mrow + 4);
            int m[8] = {m0.x, m0.y, m0.z, m0.w, m1.x, m1.y, m1.z, m1.w};
            float s[8];
            float2 f01 = unpack2(acc[i][0]);
            float2 f23 = unpack2(acc[i][1]);
            float2 f45 = unpack2(acc[i][2]);
            float2 f67 = unpack2(acc[i][3]);
            s[0] = f01.x; s[1] = f01.y; s[2] = f23.x; s[3] = f23.y;
            s[4] = f45.x; s[5] = f45.y; s[6] = f67.x; s[7] = f67.y;
#pragma unroll
            for (int j = 0; j < 8; j++) {
                s[j] = m[j] ? 0.0f : (s[j] + 1.0f);
                rs[i] += s[j];
            }
            float* arow = attn + ((size_t)b * LL + qrow) * LL + kbase;
            *(float4*)arow = make_float4(s[0], s[1], s[2], s[3]);
            *(float4*)(arow + 4) = make_float4(s[4], s[5], s[6], s[7]);
        }
    }

    // Reduce row sums across the 16 k-group lanes (contiguous half-warp groups)
#pragma unroll
    for (int i = 0; i < 4; i++) {
        float vsum = rs[i];
#pragma unroll
        for (int o = 8; o; o >>= 1) vsum += __shfl_xor_sync(0xffffffffu, vsum, o, 16);
        if (tx == 0) {
            g_rinv[(size_t)b * LL + q0 + ty * 4 + i] = 1.0f / fmaxf(vsum, 1e-12f);
        }
    }
}

// ---------- Kernel 3: rescale attn (final write) + PV GEMM ----------
// grid: (L/QT, B), 256 threads. Thread tile: 4q x 4d.
// dyn smem: s_s[64][SSP] + v_s[128][VSP]
__global__ __launch_bounds__(256) void pv_kernel(const float* __restrict__ v,
                                                 float* __restrict__ attn,
                                                 float* __restrict__ out) {
    extern __shared__ float sm[];
    float* s_s = sm;                 // scaled scores [q][k]
    float* v_s = sm + QT * SSP;      // v tile [k][d]
    __shared__ float rinv_s[QT];

    int b = blockIdx.y;
    int q0 = blockIdx.x * QT;
    int t = threadIdx.x;
    int ty = t >> 4;   // q group of 4
    int tx = t & 15;   // d group of 4

    if (t < QT) rinv_s[t] = g_rinv[(size_t)b * LL + q0 + t];

    unsigned long long acc[4][2];
#pragma unroll
    for (int i = 0; i < 4; i++) { acc[i][0] = 0ull; acc[i][1] = 0ull; }

    const float* vb = v + (size_t)b * LL * DD;

    for (int kt = 0; kt < NKT; kt++) {
        __syncthreads();
        // Stage scores: read raw, scale, write final attn, store in smem
#pragma unroll
        for (int i = 0; i < 8; i++) {
            int idx = i * 256 + t;
            int r = idx >> 5, c4 = idx & 31;
            float* ap = attn + ((size_t)b * LL + q0 + r) * LL + (size_t)kt * KTILE + c4 * 4;
            float4 x = *(float4*)ap;
            float sc = rinv_s[r];
            x.x *= sc; x.y *= sc; x.z *= sc; x.w *= sc;
            *(float4*)ap = x;
            *(float4*)&s_s[r * SSP + c4 * 4] = x;
        }
        // Stage v tile (128 rows x 64)
#pragma unroll
        for (int i = 0; i < 8; i++) {
            int idx = i * 256 + t;
            int r = idx >> 4, c4 = idx & 15;
            float4 w = *(const float4*)(vb + ((size_t)kt * KTILE + r) * DD + c4 * 4);
            *(float4*)&v_s[r * VSP + c4 * 4] = w;
        }
        __syncthreads();

        for (int k4 = 0; k4 < KTILE; k4 += 4) {
            float sarr[4][4];
#pragma unroll
            for (int i = 0; i < 4; i++) {
                float4 sv = *(const float4*)&s_s[(ty * 4 + i) * SSP + k4];
                sarr[i][0] = sv.x; sarr[i][1] = sv.y; sarr[i][2] = sv.z; sarr[i][3] = sv.w;
            }
#pragma unroll
            for (int kk = 0; kk < 4; kk++) {
                F4U2 vv;
                vv.f = *(const float4*)&v_s[(k4 + kk) * VSP + tx * 4];
#pragma unroll
                for (int i = 0; i < 4; i++) {
                    unsigned long long sq = pack2(sarr[i][kk], sarr[i][kk]);
                    fma2(acc[i][0], sq, vv.u.x);
                    fma2(acc[i][1], sq, vv.u.y);
                }
            }
        }
    }

    // Write output tile
#pragma unroll
    for (int i = 0; i < 4; i++) {
        float2 a0 = unpack2(acc[i][0]);
        float2 a1 = unpack2(acc[i][1]);
        float4 o = make_float4(a0.x, a0.y, a1.x, a1.y);
        *(float4*)(out + ((size_t)b * LL + q0 + ty * 4 + i) * DD + tx * 4) = o;
    }
}

// ---------- launch ----------
extern "C" void kernel_launch(void* const* d_in, const int* in_sizes, int n_in,
                              void* d_out, int out_size) {
    const float* q = (const float*)d_in[0];
    const float* k = (const float*)d_in[1];
    const float* v = (const float*)d_in[2];
    const int* mask = (const int*)d_in[3];

    float* out = (float*)d_out;
    float* attn = out + (size_t)BB * LL * DD;

    const int QK_SMEM = (DD * QTP + DD * KTP) * (int)sizeof(float);   // 51200
    const int PV_SMEM = (QT * SSP + KTILE * VSP) * (int)sizeof(float); // 68608

    cudaFuncSetAttribute(qk_kernel, cudaFuncAttributeMaxDynamicSharedMemorySize, QK_SMEM);
    cudaFuncSetAttribute(pv_kernel, cudaFuncAttributeMaxDynamicSharedMemorySize, PV_SMEM);

    norm_kernel<<<(2 * BB * LL) / 16, 256>>>(q, k);
    qk_kernel<<<dim3(LL / QT, BB), 256, QK_SMEM>>>(mask, attn);
    pv_kernel<<<dim3(LL / QT, BB), 256, PV_SMEM>>>(v, attn, out);
}

// round 3
// speedup vs baseline: 1.4840x; 1.4840x over previous
#include <cuda_runtime.h>
#include <cstdint>

#define BB 32
#define LL 2048
#define DD 64

// qk kernel tiling
#define QKT 64        // q rows per CTA
#define KKT 256       // k per tile
#define NKT_QK (LL / KKT)
#define QTP 68        // qT stride (floats)
#define KTP 260       // kT stride (floats)

// pv kernel tiling
#define PQT 64        // q rows per CTA
#define PKT 128       // k per tile
#define NKT_PV (LL / PKT)
#define STP 68        // sT stride (k-major, 64 q + pad)
#define VTP 68        // v_s stride

// Scratch
__device__ float g_qn[(size_t)BB * LL * DD];
__device__ float g_kn[(size_t)BB * LL * DD];
__device__ float g_rinv[(size_t)BB * LL];

// ---------- f32x2 packed helpers ----------
union F4U2 { float4 f; ulonglong2 u; };

__device__ __forceinline__ unsigned long long pack2(float lo, float hi) {
    unsigned long long r;
    asm("mov.b64 %0, {%1, %2};" : "=l"(r) : "f"(lo), "f"(hi));
    return r;
}
__device__ __forceinline__ void fma2(unsigned long long& d,
                                     unsigned long long a,
                                     unsigned long long b) {
    asm("fma.rn.f32x2 %0, %1, %2, %0;" : "+l"(d) : "l"(a), "l"(b));
}
__device__ __forceinline__ float2 unpack2(unsigned long long v) {
    float2 f;
    asm("mov.b64 {%0, %1}, %2;" : "=f"(f.x), "=f"(f.y) : "l"(v));
    return f;
}

// ---------- Kernel 1: L2-normalize q and k rows ----------
__global__ __launch_bounds__(256) void norm_kernel(const float* __restrict__ q,
                                                   const float* __restrict__ k) {
    int t = threadIdx.x;
    int rowInBlk = t >> 4;
    int lane = t & 15;
    long long row = (long long)blockIdx.x * 16 + rowInBlk;

    const float* src;
    float* dst;
    long long r2 = row;
    if (r2 < (long long)BB * LL) {
        src = q; dst = g_qn;
    } else {
        src = k; dst = g_kn; r2 -= (long long)BB * LL;
    }

    const float4 v = *(const float4*)(src + r2 * DD + lane * 4);
    float ss = v.x * v.x + v.y * v.y + v.z * v.z + v.w * v.w;
#pragma unroll
    for (int o = 8; o; o >>= 1) ss += __shfl_xor_sync(0xffffffffu, ss, o, 16);
    float inv = 1.0f / fmaxf(sqrtf(ss), 1e-12f);
    *(float4*)(dst + r2 * DD + lane * 4) =
        make_float4(v.x * inv, v.y * inv, v.z * inv, v.w * inv);
}

// ---------- Kernel 2: QK scores (raw, masked, +1) + row sums ----------
// grid (LL/QKT, BB), 256 threads, 2 CTAs/SM.
// Thread tile: 8q x 8k (k split as {tx*4..+3} and {128+tx*4..+3}).
// dyn smem: qT[64][QTP] + kT[64][KTP]
__global__ __launch_bounds__(256, 2) void qk_kernel(const int* __restrict__ mask,
                                                    float* __restrict__ attn) {
    extern __shared__ float sm[];
    float* qT = sm;                 // [d][q], stride QTP
    float* kT = sm + DD * QTP;      // [d][k], stride KTP

    const int b = blockIdx.y;
    const int q0 = blockIdx.x * QKT;
    const int t = threadIdx.x;
    const int ty = t >> 5;   // 0..7 : q group (8 rows)
    const int tx = t & 31;   // 0..31: k group

    const float* qn = g_qn + ((size_t)b * LL + q0) * DD;
    const float* kn = g_kn + (size_t)b * LL * DD;

    // Stage qT: thread loads 4 scalars of same d (lanes vary d -> coalesced),
    // stores one float4 along q (4-way bank conflict max, one-time).
#pragma unroll
    for (int g = 0; g < 4; g++) {
        int d = (t & 31) + 32 * (g & 1);
        int r4 = (t >> 5) + 8 * (g >> 1);      // 0..15
        float v0 = qn[(r4 * 4 + 0) * DD + d];
        float v1 = qn[(r4 * 4 + 1) * DD + d];
        float v2 = qn[(r4 * 4 + 2) * DD + d];
        float v3 = qn[(r4 * 4 + 3) * DD + d];
        *(float4*)&qT[d * QTP + r4 * 4] = make_float4(v0, v1, v2, v3);
    }

    float rs[8];
#pragma unroll
    for (int i = 0; i < 8; i++) rs[i] = 0.f;

    for (int kt = 0; kt < NKT_QK; kt++) {
        __syncthreads();
        // Stage kT (256 k rows x 64 d), same d-major trick
#pragma unroll
        for (int g = 0; g < 16; g++) {
            int d = (t & 31) + 32 * (g & 1);
            int r4 = (t >> 5) + 8 * (g >> 1);  // 0..63
            const float* kp = kn + ((size_t)kt * KKT + r4 * 4) * DD + d;
            float v0 = kp[0 * DD];
            float v1 = kp[1 * DD];
            float v2 = kp[2 * DD];
            float v3 = kp[3 * DD];
            *(float4*)&kT[d * KTP + r4 * 4] = make_float4(v0, v1, v2, v3);
        }
        __syncthreads();

        unsigned long long acc[8][4];
#pragma unroll
        for (int i = 0; i < 8; i++)
#pragma unroll
            for (int j = 0; j < 4; j++) acc[i][j] = 0ull;

#pragma unroll 8
        for (int d = 0; d < DD; d++) {
            float4 qa = *(const float4*)&qT[d * QTP + ty * 8];       // broadcast
            float4 qb = *(const float4*)&qT[d * QTP + ty * 8 + 4];
            F4U2 ka, kb;
            ka.f = *(const float4*)&kT[d * KTP + tx * 4];
            kb.f = *(const float4*)&kT[d * KTP + 128 + tx * 4];
            float qv[8] = {qa.x, qa.y, qa.z, qa.w, qb.x, qb.y, qb.z, qb.w};
#pragma unroll
            for (int i = 0; i < 8; i++) {
                unsigned long long qq = pack2(qv[i], qv[i]);
                fma2(acc[i][0], qq, ka.u.x);
                fma2(acc[i][1], qq, ka.u.y);
                fma2(acc[i][2], qq, kb.u.x);
                fma2(acc[i][3], qq, kb.u.y);
            }
        }

        // Epilogue: mask (int32), +1, write raw scores, accumulate row sums
        size_t kb1 = (size_t)kt * KKT + tx * 4;
        size_t kb2 = kb1 + 128;
#pragma unroll
        for (int i = 0; i < 8; i++) {
            int qrow = q0 + ty * 8 + i;
            const int* mrow = mask + ((size_t)b * LL + qrow) * LL;
            int4 m0 = *(const int4*)(mrow + kb1);
            int4 m1 = *(const int4*)(mrow + kb2);
            float2 f01 = unpack2(acc[i][0]);
            float2 f23 = unpack2(acc[i][1]);
            float2 f45 = unpack2(acc[i][2]);
            float2 f67 = unpack2(acc[i][3]);
            float s0 = m0.x ? 0.f : (f01.x + 1.f);
            float s1 = m0.y ? 0.f : (f01.y + 1.f);
            float s2 = m0.z ? 0.f : (f23.x + 1.f);
            float s3 = m0.w ? 0.f : (f23.y + 1.f);
            float s4 = m1.x ? 0.f : (f45.x + 1.f);
            float s5 = m1.y ? 0.f : (f45.y + 1.f);
            float s6 = m1.z ? 0.f : (f67.x + 1.f);
            float s7 = m1.w ? 0.f : (f67.y + 1.f);
            rs[i] += ((s0 + s1) + (s2 + s3)) + ((s4 + s5) + (s6 + s7));
            float* arow = attn + ((size_t)b * LL + qrow) * LL;
            *(float4*)(arow + kb1) = make_float4(s0, s1, s2, s3);
            *(float4*)(arow + kb2) = make_float4(s4, s5, s6, s7);
        }
    }

    // Row-sum reduce: each warp spans the full k range -> full-warp reduce
#pragma unroll
    for (int i = 0; i < 8; i++) {
        float vsum = rs[i];
#pragma unroll
        for (int o = 16; o; o >>= 1) vsum += __shfl_xor_sync(0xffffffffu, vsum, o);
        if (tx == 0) {
            g_rinv[(size_t)b * LL + q0 + ty * 8 + i] = 1.0f / fmaxf(vsum, 1e-12f);
        }
    }
}

// ---------- Kernel 3: rescale attn (final write) + PV GEMM ----------
// grid (LL/PQT, BB), 128 threads, 3 CTAs/SM.
// Thread tile: 8q x 4d. Scores staged k-major sT[k][q] for broadcast reads.
// dyn smem: sT[PKT][STP] + v_s[PKT][VTP]
__global__ __launch_bounds__(128, 3) void pv_kernel(const float* __restrict__ v,
                                                    float* __restrict__ attn,
                                                    float* __restrict__ out) {
    extern __shared__ float sm[];
    float* sT = sm;                  // [k][q], stride STP
    float* v_s = sm + PKT * STP;     // [k][d], stride VTP
    __shared__ float rinv_s[PQT];

    const int b = blockIdx.y;
    const int q0 = blockIdx.x * PQT;
    const int t = threadIdx.x;
    const int qg = t >> 4;   // 0..7 : q group (8 rows)
    const int dg = t & 15;   // 0..15: d group (4 cols)

    if (t < PQT) rinv_s[t] = g_rinv[(size_t)b * LL + q0 + t];

    unsigned long long acc[8][2];
#pragma unroll
    for (int i = 0; i < 8; i++) { acc[i][0] = 0ull; acc[i][1] = 0ull; }

    const float* vb = v + (size_t)b * LL * DD;
    float* ab = attn + ((size_t)b * LL + q0) * LL;

    for (int kt = 0; kt < NKT_PV; kt++) {
        __syncthreads();
        // Stage sT: read raw attn (coalesced scalar, lanes vary k), scale,
        // write final attn back, store transposed float4 along q.
#pragma unroll
        for (int i = 0; i < 16; i++) {
            int kloc = (t & 31) + 32 * (i & 3);          // 0..127
            int q4 = (t >> 5) + 4 * (i >> 2);            // 0..15
            float* gp = ab + (size_t)(q4 * 4) * LL + (size_t)kt * PKT + kloc;
            float x0 = gp[0 * LL] * rinv_s[q4 * 4 + 0];
            float x1 = gp[1 * LL] * rinv_s[q4 * 4 + 1];
            float x2 = gp[2 * LL] * rinv_s[q4 * 4 + 2];
            float x3 = gp[3 * LL] * rinv_s[q4 * 4 + 3];
            gp[0 * LL] = x0; gp[1 * LL] = x1; gp[2 * LL] = x2; gp[3 * LL] = x3;
            *(float4*)&sT[kloc * STP + q4 * 4] = make_float4(x0, x1, x2, x3);
        }
        // Stage v tile (128 x 64), row-major
#pragma unroll
        for (int i = 0; i < 16; i++) {
            int idx = i * 128 + t;
            int r = idx >> 4, c4 = idx & 15;
            *(float4*)&v_s[r * VTP + c4 * 4] =
                *(const float4*)(vb + ((size_t)kt * PKT + r) * DD + c4 * 4);
        }
        __syncthreads();

#pragma unroll 4
        for (int kk = 0; kk < PKT; kk++) {
            float4 sa = *(const float4*)&sT[kk * STP + qg * 8];      // broadcast
            float4 sb = *(const float4*)&sT[kk * STP + qg * 8 + 4];
            F4U2 vv;
            vv.f = *(const float4*)&v_s[kk * VTP + dg * 4];
            float sv[8] = {sa.x, sa.y, sa.z, sa.w, sb.x, sb.y, sb.z, sb.w};
#pragma unroll
            for (int i = 0; i < 8; i++) {
                unsigned long long sq = pack2(sv[i], sv[i]);
                fma2(acc[i][0], sq, vv.u.x);
                fma2(acc[i][1], sq, vv.u.y);
            }
        }
    }

    // Write output tile: 8q x 4d per thread
#pragma unroll
    for (int i = 0; i < 8; i++) {
        float2 a0 = unpack2(acc[i][0]);
        float2 a1 = unpack2(acc[i][1]);
        *(float4*)(out + ((size_t)b * LL + q0 + qg * 8 + i) * DD + dg * 4) =
            make_float4(a0.x, a0.y, a1.x, a1.y);
    }
}

// ---------- launch ----------
extern "C" void kernel_launch(void* const* d_in, const int* in_sizes, int n_in,
                              void* d_out, int out_size) {
    const float* q = (const float*)d_in[0];
    const float* k = (const float*)d_in[1];
    const float* v = (const float*)d_in[2];
    const int* mask = (const int*)d_in[3];

    float* out = (float*)d_out;
    float* attn = out + (size_t)BB * LL * DD;

    const int QK_SMEM = (DD * QTP + DD * KTP) * (int)sizeof(float);   // 83968
    const int PV_SMEM = (PKT * STP + PKT * VTP) * (int)sizeof(float); // 69632

    cudaFuncSetAttribute(qk_kernel, cudaFuncAttributeMaxDynamicSharedMemorySize, QK_SMEM);
    cudaFuncSetAttribute(pv_kernel, cudaFuncAttributeMaxDynamicSharedMemorySize, PV_SMEM);

    norm_kernel<<<(2 * BB * LL) / 16, 256>>>(q, k);
    qk_kernel<<<dim3(LL / QKT, BB), 256, QK_SMEM>>>(mask, attn);
    pv_kernel<<<dim3(LL / PQT, BB), 128, PV_SMEM>>>(v, attn, out);
}

// round 5
// speedup vs baseline: 1.5490x; 1.0438x over previous
#include <cuda_runtime.h>
#include <cstdint>

#define BB 32
#define LL 2048
#define DD 64

#define QKQ 128          // q rows per CTA (both GEMM kernels)
#define KT  64           // k per tile
#define NKT (LL / KT)    // 32
#define QSP 68           // [128 x 68] score/q operand stride
#define KSP 68           // [64 x 68] k/v operand stride

__device__ float g_qn[(size_t)BB * LL * DD];   // tf32-rounded normalized q
__device__ float g_kn[(size_t)BB * LL * DD];   // tf32-rounded normalized k
__device__ float g_rinv[(size_t)BB * LL];

// ---------------- helpers ----------------
__device__ __forceinline__ uint32_t f2tf32(float x) {
    uint32_t u;
    asm("cvt.rna.tf32.f32 %0, %1;" : "=r"(u) : "f"(x));
    return u;
}
__device__ __forceinline__ void mma_tf32(float* c, const uint32_t* a, const uint32_t* b) {
    asm volatile(
        "mma.sync.aligned.m16n8k8.row.col.f32.tf32.tf32.f32 "
        "{%0,%1,%2,%3}, {%4,%5,%6,%7}, {%8,%9}, {%0,%1,%2,%3};"
        : "+f"(c[0]), "+f"(c[1]), "+f"(c[2]), "+f"(c[3])
        : "r"(a[0]), "r"(a[1]), "r"(a[2]), "r"(a[3]), "r"(b[0]), "r"(b[1]));
}

// ---------- Kernel 1: L2-normalize q,k rows; output rounded to tf32 ----------
__global__ __launch_bounds__(256) void norm_kernel(const float* __restrict__ q,
                                                   const float* __restrict__ k) {
    int t = threadIdx.x;
    int rowInBlk = t >> 4;
    int lane = t & 15;
    long long row = (long long)blockIdx.x * 16 + rowInBlk;

    const float* src;
    float* dst;
    long long r2 = row;
    if (r2 < (long long)BB * LL) {
        src = q; dst = g_qn;
    } else {
        src = k; dst = g_kn; r2 -= (long long)BB * LL;
    }
    const float4 v = *(const float4*)(src + r2 * DD + lane * 4);
    float ss = v.x * v.x + v.y * v.y + v.z * v.z + v.w * v.w;
#pragma unroll
    for (int o = 8; o; o >>= 1) ss += __shfl_xor_sync(0xffffffffu, ss, o, 16);
    float inv = 1.0f / fmaxf(sqrtf(ss), 1e-12f);
    float4 o4;
    o4.x = __uint_as_float(f2tf32(v.x * inv));
    o4.y = __uint_as_float(f2tf32(v.y * inv));
    o4.z = __uint_as_float(f2tf32(v.z * inv));
    o4.w = __uint_as_float(f2tf32(v.w * inv));
    *(float4*)(dst + r2 * DD + lane * 4) = o4;
}

// ---------- Kernel 2: QK scores via tf32 HMMA; raw masked (+1) + rowsums ----------
// grid (LL/QKQ=16, BB), 256 threads (8 warps). Warp w: mi=w&3 (32q), ni=w>>2 (32k).
__global__ __launch_bounds__(256, 2) void qk_kernel(const int* __restrict__ mask,
                                                    float* __restrict__ attn) {
    extern __shared__ float sm[];
    float* qs = sm;                     // [128][QSP]
    float* ks = sm + 128 * QSP;         // [64][KSP]
    float* part = ks + 64 * KSP;        // [128][2]

    const int b = blockIdx.y;
    const int q0 = blockIdx.x * QKQ;
    const int t = threadIdx.x;
    const int w = t >> 5, lane = t & 31;
    const int g = lane >> 2, c = lane & 3;
    const int mi = w & 3, ni = w >> 2;
    const int m0 = mi * 32, n0 = ni * 32;

    // stage q tile (already tf32 bits)
    {
        int r = t >> 1, h = t & 1;
        const float4* src = (const float4*)(g_qn + ((size_t)b * LL + q0 + r) * DD + h * 32);
#pragma unroll
        for (int i = 0; i < 8; i++)
            *(float4*)&qs[r * QSP + h * 32 + i * 4] = src[i];
    }
    const float* kn = g_kn + (size_t)b * LL * DD;

    float rs[4] = {0.f, 0.f, 0.f, 0.f};

    const int kr = t >> 2, kq = t & 3;
    for (int kt = 0; kt < NKT; kt++) {
        // prefetch k tile 64x64
        const float4* ksrc = (const float4*)(kn + ((size_t)kt * KT + kr) * DD + kq * 16);
        float4 kv0 = ksrc[0], kv1 = ksrc[1], kv2 = ksrc[2], kv3 = ksrc[3];
        __syncthreads();
        *(float4*)&ks[kr * KSP + kq * 16 + 0]  = kv0;
        *(float4*)&ks[kr * KSP + kq * 16 + 4]  = kv1;
        *(float4*)&ks[kr * KSP + kq * 16 + 8]  = kv2;
        *(float4*)&ks[kr * KSP + kq * 16 + 12] = kv3;
        __syncthreads();

        float acc[2][4][4];
#pragma unroll
        for (int mf = 0; mf < 2; mf++)
#pragma unroll
            for (int nf = 0; nf < 4; nf++)
#pragma unroll
                for (int e = 0; e < 4; e++) acc[mf][nf][e] = 0.f;

#pragma unroll
        for (int s = 0; s < 8; s++) {
            uint32_t a[2][4];
#pragma unroll
            for (int mf = 0; mf < 2; mf++) {
                int rbase = (m0 + mf * 16 + g) * QSP + s * 8 + c;
                a[mf][0] = __float_as_uint(qs[rbase]);
                a[mf][1] = __float_as_uint(qs[rbase + 8 * QSP]);
                a[mf][2] = __float_as_uint(qs[rbase + 4]);
                a[mf][3] = __float_as_uint(qs[rbase + 8 * QSP + 4]);
            }
#pragma unroll
            for (int nf = 0; nf < 4; nf++) {
                int nbase = (n0 + nf * 8 + g) * KSP + s * 8 + c;
                uint32_t bb[2];
                bb[0] = __float_as_uint(ks[nbase]);
                bb[1] = __float_as_uint(ks[nbase + 4]);
                mma_tf32(acc[0][nf], a[0], bb);
                mma_tf32(acc[1][nf], a[1], bb);
            }
        }

        // epilogue: mask (int32), +1, raw write, rowsums
#pragma unroll
        for (int mf = 0; mf < 2; mf++) {
            int row0 = q0 + m0 + mf * 16 + g;
            const int* mr0 = mask + ((size_t)b * LL + row0) * LL;
            const int* mr1 = mr0 + (size_t)8 * LL;
            float* ar0 = attn + ((size_t)b * LL + row0) * LL;
            float* ar1 = ar0 + (size_t)8 * LL;
#pragma unroll
            for (int nf = 0; nf < 4; nf++) {
                size_t col = (size_t)kt * KT + n0 + nf * 8 + 2 * c;
                int2 mA = *(const int2*)(mr0 + col);
                int2 mB = *(const int2*)(mr1 + col);
                float s0 = mA.x ? 0.f : acc[mf][nf][0] + 1.f;
                float s1 = mA.y ? 0.f : acc[mf][nf][1] + 1.f;
                float s2 = mB.x ? 0.f : acc[mf][nf][2] + 1.f;
                float s3 = mB.y ? 0.f : acc[mf][nf][3] + 1.f;
                *(float2*)(ar0 + col) = make_float2(s0, s1);
                *(float2*)(ar1 + col) = make_float2(s2, s3);
                rs[mf * 2 + 0] += s0 + s1;
                rs[mf * 2 + 1] += s2 + s3;
            }
        }
    }

    // reduce rowsums: lanes c=0..3 hold same rows
#pragma unroll
    for (int i = 0; i < 4; i++) {
        float vsum = rs[i];
        vsum += __shfl_xor_sync(0xffffffffu, vsum, 1);
        vsum += __shfl_xor_sync(0xffffffffu, vsum, 2);
        rs[i] = vsum;
    }
    if (c == 0) {
        part[(m0 + g) * 2 + ni]      = rs[0];
        part[(m0 + g + 8) * 2 + ni]  = rs[1];
        part[(m0 + g + 16) * 2 + ni] = rs[2];
        part[(m0 + g + 24) * 2 + ni] = rs[3];
    }
    __syncthreads();
    if (t < 128)
        g_rinv[(size_t)b * LL + q0 + t] =
            1.0f / fmaxf(part[t * 2] + part[t * 2 + 1], 1e-12f);
}

// ---------- Kernel 3: rescale attn + PV GEMM (tf32 HMMA, V split hi/lo) ----------
// grid (16, BB), 256 threads. Warp w: mi=w&3 (32q), ni=w>>2 (32d).
__global__ __launch_bounds__(256, 2) void pv_kernel(const float* __restrict__ v,
                                                    float* __restrict__ attn,
                                                    float* __restrict__ out) {
    extern __shared__ float sm[];
    float* ss = sm;                     // [128][QSP] tf32 scores
    float* vh = sm + 128 * QSP;         // [64 d][KSP] tf32 hi
    float* vl = vh + 64 * KSP;          // [64 d][KSP] tf32 lo
    float* rinv = vl + 64 * KSP;        // [128]

    const int b = blockIdx.y;
    const int q0 = blockIdx.x * QKQ;
    const int t = threadIdx.x;
    const int w = t >> 5, lane = t & 31;
    const int g = lane >> 2, c = lane & 3;
    const int mi = w & 3, ni = w >> 2;
    const int m0 = mi * 32, n0 = ni * 32;

    if (t < 128) rinv[t] = g_rinv[(size_t)b * LL + q0 + t];

    float acc[2][4][4];
#pragma unroll
    for (int mf = 0; mf < 2; mf++)
#pragma unroll
        for (int nf = 0; nf < 4; nf++)
#pragma unroll
            for (int e = 0; e < 4; e++) acc[mf][nf][e] = 0.f;

    const float* vb = v + (size_t)b * LL * DD;
    const int ar = t >> 1, ah = t & 1;      // attn staging: row, half
    const int vd = t & 63, vq = t >> 6;     // v staging: d, k-quarter
    float* abase = attn + ((size_t)b * LL + q0 + ar) * LL + ah * 32;

    __syncthreads();

    for (int kt = 0; kt < NKT; kt++) {
        // prefetch raw attn (8 float4 per thread)
        float4 araw[8];
        float* ap = abase + (size_t)kt * KT;
#pragma unroll
        for (int i = 0; i < 8; i++) araw[i] = *(float4*)(ap + i * 4);

        __syncthreads();   // previous GEMM done reading smem

        // scale, write final attn, store tf32 scores
        float ri = rinv[ar];
#pragma unroll
        for (int i = 0; i < 8; i++) {
            float4 x = araw[i];
            x.x *= ri; x.y *= ri; x.z *= ri; x.w *= ri;
            *(float4*)(ap + i * 4) = x;
            float4 tx;
            tx.x = __uint_as_float(f2tf32(x.x));
            tx.y = __uint_as_float(f2tf32(x.y));
            tx.z = __uint_as_float(f2tf32(x.z));
            tx.w = __uint_as_float(f2tf32(x.w));
            *(float4*)&ss[ar * QSP + ah * 32 + i * 4] = tx;
        }
        // stage v transposed hi/lo: vh/vl[d][k]
#pragma unroll
        for (int j = 0; j < 16; j++) {
            int kk = vq * 16 + j;
            float x = vb[((size_t)kt * KT + kk) * DD + vd];
            uint32_t hb = f2tf32(x);
            float hif = __uint_as_float(hb);
            uint32_t lb = f2tf32(x - hif);
            vh[vd * KSP + kk] = __uint_as_float(hb);
            vl[vd * KSP + kk] = __uint_as_float(lb);
        }
        __syncthreads();

        // GEMM: out += S * (Vh + Vl)
#pragma unroll
        for (int s = 0; s < 8; s++) {
            uint32_t a[2][4];
#pragma unroll
            for (int mf = 0; mf < 2; mf++) {
                int rbase = (m0 + mf * 16 + g) * QSP + s * 8 + c;
                a[mf][0] = __float_as_uint(ss[rbase]);
                a[mf][1] = __float_as_uint(ss[rbase + 8 * QSP]);
                a[mf][2] = __float_as_uint(ss[rbase + 4]);
                a[mf][3] = __float_as_uint(ss[rbase + 8 * QSP + 4]);
            }
#pragma unroll
            for (int nf = 0; nf < 4; nf++) {
                int nbase = (n0 + nf * 8 + g) * KSP + s * 8 + c;
                uint32_t bh[2], bl[2];
                bh[0] = __float_as_uint(vh[nbase]);
                bh[1] = __float_as_uint(vh[nbase + 4]);
                bl[0] = __float_as_uint(vl[nbase]);
                bl[1] = __float_as_uint(vl[nbase + 4]);
                mma_tf32(acc[0][nf], a[0], bh);
                mma_tf32(acc[1][nf], a[1], bh);
                mma_tf32(acc[0][nf], a[0], bl);
                mma_tf32(acc[1][nf], a[1], bl);
            }
        }
    }

    // epilogue: write out tile
#pragma unroll
    for (int mf = 0; mf < 2; mf++) {
        int row0 = q0 + m0 + mf * 16 + g;
        float* o0 = out + (size_t)((size_t)b * LL + row0) * DD;
        float* o1 = o0 + (size_t)8 * DD;
#pragma unroll
        for (int nf = 0; nf < 4; nf++) {
            int col = n0 + nf * 8 + 2 * c;
            *(float2*)(o0 + col) = make_float2(acc[mf][nf][0], acc[mf][nf][1]);
            *(float2*)(o1 + col) = make_float2(acc[mf][nf][2], acc[mf][nf][3]);
        }
    }
}

// ---------------- launch ----------------
extern "C" void kernel_launch(void* const* d_in, const int* in_sizes, int n_in,
                              void* d_out, int out_size) {
    const float* q = (const float*)d_in[0];
    const float* k = (const float*)d_in[1];
    const float* v = (const float*)d_in[2];
    const int* mask = (const int*)d_in[3];

    float* out = (float*)d_out;
    float* attn = out + (size_t)BB * LL * DD;

    const int QK_SMEM = (128 * QSP + 64 * KSP + 256) * (int)sizeof(float);
    const int PV_SMEM = (128 * QSP + 2 * 64 * KSP + 128) * (int)sizeof(float);

    cudaFuncSetAttribute(qk_kernel, cudaFuncAttributeMaxDynamicSharedMemorySize, QK_SMEM);
    cudaFuncSetAttribute(pv_kernel, cudaFuncAttributeMaxDynamicSharedMemorySize, PV_SMEM);

    norm_kernel<<<(2 * BB * LL) / 16, 256>>>(q, k);
    qk_kernel<<<dim3(LL / QKQ, BB), 256, QK_SMEM>>>(mask, attn);
    pv_kernel<<<dim3(LL / QKQ, BB), 256, PV_SMEM>>>(v, attn, out);
}